// round 12
// baseline (speedup 1.0000x reference)
#include <cuda_runtime.h>
#include <cstdint>
#include <cstddef>

// Problem dims
#define BB   128      // batch
#define SS   200      // seq
#define VV   1400     // vocab
#define DD   256      // input/hidden dim
#define HH   256
#define G4   1024     // 4*H
#define NC   128      // classes

// ---------------- device scratch (static, no allocs) ----------------
__device__ __align__(16) float g_embedded[BB * SS * DD];   // [b][s][d]
__device__ __align__(16) float g_ux[2][SS * G4 * BB];      // [l][s][e][b]
__device__ __align__(16) float g_hs[2][SS * HH * BB];      // [l][t][j][b]
__device__ __align__(16) float g_hbuf[2][2][HH * BB];      // [phase][l][j][b]
__device__ __align__(16) float g_cbuf[2][2][HH * BB];
__device__ __align__(16) float g_tsT[SS * BB];             // [t][b]
__device__ __align__(16) float g_alpha[BB * SS];
__device__ __align__(16) float g_beta[SS * DD * BB];       // [s][d][b]
__device__ __align__(16) float g_ctx[BB * DD];

// ---------------- helpers ----------------
__device__ __forceinline__ float sigf(float x) { return 1.0f / (1.0f + __expf(-x)); }

// ---------------- init: state transpose, ts transpose ----------------
__global__ void init_kernel(const float* __restrict__ h01, const float* __restrict__ c01,
                            const float* __restrict__ h02, const float* __restrict__ c02,
                            const float* __restrict__ tsp) {
    int gid = blockIdx.x * blockDim.x + threadIdx.x;
    int stride = gridDim.x * blockDim.x;
    for (int i = gid; i < HH * BB; i += stride) {
        int j = i >> 7, r = i & 127;                 // [j][r] <- [r][j]
        g_hbuf[0][0][i] = h01[r * HH + j];
        g_cbuf[0][0][i] = c01[r * HH + j];
        g_hbuf[0][1][i] = h02[r * HH + j];
        g_cbuf[0][1][i] = c02[r * HH + j];
    }
    for (int i = gid; i < SS * BB; i += stride) {
        int t = i >> 7, r = i & 127;
        g_tsT[i] = tsp[r * SS + t];
    }
}

// ---------------- K1: embedded = inputs @ emb ----------------
// C[M=25600][256] = A[M][1400] * W[1400][256].  BM=128 BN=64 BK=8, 8x4 microtile
__global__ __launch_bounds__(256) void embed_gemm(const float* __restrict__ A,
                                                  const float* __restrict__ W) {
    const int m0 = blockIdx.y * 128;
    const int n0 = blockIdx.x * 64;
    __shared__ __align__(16) float As[8][128];
    __shared__ __align__(16) float Bs[8][64];
    const int tid = threadIdx.x;
    const int a_m = tid >> 1, a_k = (tid & 1) * 4;
    const int b_k = tid >> 5, b_n = (tid & 31) * 2;
    const int tx = tid & 15, ty = tid >> 4;
    float acc[8][4];
#pragma unroll
    for (int i = 0; i < 8; ++i)
#pragma unroll
        for (int jx = 0; jx < 4; ++jx) acc[i][jx] = 0.0f;

    const float* Ap = A + (size_t)(m0 + a_m) * VV + a_k;
    const float* Bp = W + (size_t)b_k * DD + n0 + b_n;

    for (int k0 = 0; k0 < VV; k0 += 8) {
        float4 av = *(const float4*)(Ap + k0);
        float2 bv = *(const float2*)(Bp + (size_t)k0 * DD);
        __syncthreads();
        As[a_k + 0][a_m] = av.x; As[a_k + 1][a_m] = av.y;
        As[a_k + 2][a_m] = av.z; As[a_k + 3][a_m] = av.w;
        Bs[b_k][b_n] = bv.x; Bs[b_k][b_n + 1] = bv.y;
        __syncthreads();
#pragma unroll
        for (int k = 0; k < 8; ++k) {
            float a[8], bq[4];
            *(float4*)&a[0] = *(const float4*)&As[k][ty * 8];
            *(float4*)&a[4] = *(const float4*)&As[k][ty * 8 + 4];
            *(float4*)&bq[0] = *(const float4*)&Bs[k][tx * 4];
#pragma unroll
            for (int i = 0; i < 8; ++i)
#pragma unroll
                for (int jx = 0; jx < 4; ++jx) acc[i][jx] += a[i] * bq[jx];
        }
    }
#pragma unroll
    for (int i = 0; i < 8; ++i) {
        float4 v = make_float4(acc[i][0], acc[i][1], acc[i][2], acc[i][3]);
        *(float4*)&g_embedded[(size_t)(m0 + ty * 8 + i) * DD + n0 + tx * 4] = v;
    }
}

// ---------------- K2: ux[l][s][e][b] = U_l @ embedded_s^T + (Uall_b + Wall_b) ----------------
// per (l,s): M=1024(e) N=128(b) K=256(d).  BM=128 BN=64 BK=16
__global__ __launch_bounds__(256) void ux_gemm(
    const float* __restrict__ U1, const float* __restrict__ Ub1, const float* __restrict__ Wb1,
    const float* __restrict__ U2, const float* __restrict__ Ub2, const float* __restrict__ Wb2) {
    const int l = blockIdx.z / SS;
    const int s = blockIdx.z % SS;
    const float* U  = l ? U2  : U1;
    const float* bu = l ? Ub2 : Ub1;
    const float* bw = l ? Wb2 : Wb1;
    const int e0 = blockIdx.y * 128;
    const int n0 = blockIdx.x * 64;
    __shared__ __align__(16) float As[16][128];
    __shared__ __align__(16) float Bs[16][64];
    const int tid = threadIdx.x;
    const int a_m = tid >> 1, a_k = (tid & 1) * 8;
    const int b_n = tid >> 2, b_k = (tid & 3) * 4;
    const int tx = tid & 15, ty = tid >> 4;
    float acc[8][4];
#pragma unroll
    for (int i = 0; i < 8; ++i)
#pragma unroll
        for (int jx = 0; jx < 4; ++jx) acc[i][jx] = 0.0f;

    const float* Ap = U + (size_t)(e0 + a_m) * DD + a_k;
    const float* Bp = g_embedded + (size_t)(n0 + b_n) * (SS * DD) + s * DD + b_k;

    for (int k0 = 0; k0 < DD; k0 += 16) {
        float4 av0 = *(const float4*)(Ap + k0);
        float4 av1 = *(const float4*)(Ap + k0 + 4);
        float4 bv  = *(const float4*)(Bp + k0);
        __syncthreads();
        As[a_k + 0][a_m] = av0.x; As[a_k + 1][a_m] = av0.y;
        As[a_k + 2][a_m] = av0.z; As[a_k + 3][a_m] = av0.w;
        As[a_k + 4][a_m] = av1.x; As[a_k + 5][a_m] = av1.y;
        As[a_k + 6][a_m] = av1.z; As[a_k + 7][a_m] = av1.w;
        Bs[b_k + 0][b_n] = bv.x; Bs[b_k + 1][b_n] = bv.y;
        Bs[b_k + 2][b_n] = bv.z; Bs[b_k + 3][b_n] = bv.w;
        __syncthreads();
#pragma unroll
        for (int k = 0; k < 16; ++k) {
            float a[8], bq[4];
            *(float4*)&a[0] = *(const float4*)&As[k][ty * 8];
            *(float4*)&a[4] = *(const float4*)&As[k][ty * 8 + 4];
            *(float4*)&bq[0] = *(const float4*)&Bs[k][tx * 4];
#pragma unroll
            for (int i = 0; i < 8; ++i)
#pragma unroll
                for (int jx = 0; jx < 4; ++jx) acc[i][jx] += a[i] * bq[jx];
        }
    }
    float* uxl = g_ux[l];
#pragma unroll
    for (int i = 0; i < 8; ++i) {
        int e = e0 + ty * 8 + i;
        float bias = bu[e] + bw[e];
        float4 v = make_float4(acc[i][0] + bias, acc[i][1] + bias,
                               acc[i][2] + bias, acc[i][3] + bias);
        *(float4*)&uxl[((size_t)s * G4 + e) * BB + n0 + tx * 4] = v;
    }
}

// ---------------- one recurrence step (both LSTMs) ----------------
// 128 blocks: l = blk>>6, unit group j0 = (blk&63)*4.
// Thread: unit j0+(tid>>6), batch rows (tid&63)*2, +1.
// No grid barrier: one kernel launch per time step; kernel boundary orders steps.
__global__ __launch_bounds__(256) void step_kernel(
    const float* __restrict__ Wall1, const float* __restrict__ Wd1w, const float* __restrict__ Wd1b,
    const float* __restrict__ Wall2, const float* __restrict__ Wd2w, const float* __restrict__ Wd2b,
    int t) {
    const int l  = blockIdx.x >> 6;
    const int j0 = (blockIdx.x & 63) * 4;
    const float* Wall = l ? Wall2 : Wall1;
    const float* Wd   = l ? Wd2w : Wd1w;
    const float* Wdb  = l ? Wd2b : Wd1b;

    __shared__ __align__(16) float ws[4][4][256];   // [gate][unit][k]
    __shared__ __align__(16) float wds[4][256];     // [unit][k]
    __shared__ float bds[4];

    const int tid = threadIdx.x;
    // stage weights (vectorized: 5120 floats = 1280 float4, 5 per thread)
    for (int idx = tid; idx < 1024; idx += 256) {
        int g = idx >> 8, jj = (idx >> 6) & 3, k4 = idx & 63;
        *(float4*)&ws[g][jj][k4 * 4] =
            *(const float4*)&Wall[((size_t)((g << 8) + j0 + jj)) * DD + k4 * 4];
    }
    for (int idx = tid; idx < 256; idx += 256) {
        int jj = idx >> 6, k4 = idx & 63;
        *(float4*)&wds[jj][k4 * 4] = *(const float4*)&Wd[(size_t)(j0 + jj) * DD + k4 * 4];
    }
    if (tid < 4) bds[tid] = Wdb[j0 + tid];
    __syncthreads();

    const int jj = tid >> 6;             // 0..3
    const int j  = j0 + jj;
    const int r0 = (tid & 63) * 2;       // batch pair
    const float bd = bds[jj];
    const float* wF = &ws[0][jj][0];
    const float* wI = &ws[1][jj][0];
    const float* wO = &ws[2][jj][0];
    const float* wC = &ws[3][jj][0];
    const float* wD = &wds[jj][0];

    const int pb = t & 1;
    const float* hp = g_hbuf[pb][l];
    const float* cp = g_cbuf[pb][l];
    float* hw = g_hbuf[pb ^ 1][l];
    float* cw = g_cbuf[pb ^ 1][l];

    float aF0 = 0.f, aF1 = 0.f, aI0 = 0.f, aI1 = 0.f, aO0 = 0.f;
    float aO1 = 0.f, aC0 = 0.f, aC1 = 0.f, aD0 = 0.f, aD1 = 0.f;

    for (int k4 = 0; k4 < 64; ++k4) {
        float wfv[4], wiv[4], wov[4], wcv[4], wdv[4];
        *(float4*)wfv = *(const float4*)(wF + 4 * k4);
        *(float4*)wiv = *(const float4*)(wI + 4 * k4);
        *(float4*)wov = *(const float4*)(wO + 4 * k4);
        *(float4*)wcv = *(const float4*)(wC + 4 * k4);
        *(float4*)wdv = *(const float4*)(wD + 4 * k4);
        const float* hk = hp + (4 * k4) * BB + r0;
        const float* ck = cp + (4 * k4) * BB + r0;
#pragma unroll
        for (int kk = 0; kk < 4; ++kk) {
            float2 h2 = *(const float2*)(hk + kk * BB);
            float2 c2 = *(const float2*)(ck + kk * BB);
            aF0 += h2.x * wfv[kk]; aF1 += h2.y * wfv[kk];
            aI0 += h2.x * wiv[kk]; aI1 += h2.y * wiv[kk];
            aO0 += h2.x * wov[kk]; aO1 += h2.y * wov[kk];
            aC0 += h2.x * wcv[kk]; aC1 += h2.y * wcv[kk];
            aD0 += c2.x * wdv[kk]; aD1 += c2.y * wdv[kk];
        }
    }

    const float* uxp = g_ux[l] + ((size_t)t * G4 + j) * BB + r0;
    float2 uf = __ldcs((const float2*)(uxp + 0 * 256 * BB));
    float2 ui = __ldcs((const float2*)(uxp + 1 * 256 * BB));
    float2 uo = __ldcs((const float2*)(uxp + 2 * 256 * BB));
    float2 uc = __ldcs((const float2*)(uxp + 3 * 256 * BB));
    float2 ts2 = *(const float2*)(g_tsT + t * BB + r0);
    float2 co  = *(const float2*)(cp + j * BB + r0);

    float csx0 = tanhf(aD0 + bd), csx1 = tanhf(aD1 + bd);
    float ca0 = co.x + csx0 * (ts2.x - 1.0f);
    float ca1 = co.y + csx1 * (ts2.y - 1.0f);
    float f0 = sigf(aF0 + uf.x), f1 = sigf(aF1 + uf.y);
    float i0 = sigf(aI0 + ui.x), i1 = sigf(aI1 + ui.y);
    float o0 = sigf(aO0 + uo.x), o1 = sigf(aO1 + uo.y);
    float q0 = sigf(aC0 + uc.x), q1 = sigf(aC1 + uc.y);
    float cn0 = f0 * ca0 + i0 * q0, cn1 = f1 * ca1 + i1 * q1;
    float hn0 = o0 * tanhf(cn0),    hn1 = o1 * tanhf(cn1);

    *(float2*)(cw + j * BB + r0) = make_float2(cn0, cn1);
    *(float2*)(hw + j * BB + r0) = make_float2(hn0, hn1);
    *(float2*)(g_hs[l] + ((size_t)t * HH + j) * BB + r0) = make_float2(hn0, hn1);
}

// ---------------- alpha: E = out1 . wa ; softmax over seq ----------------
__global__ __launch_bounds__(256) void alpha_kernel(const float* __restrict__ wa) {
    const int b = blockIdx.x;
    __shared__ float was[256];
    __shared__ float Es[224];
    __shared__ float red[256];
    const int tid = threadIdx.x;
    was[tid] = wa[tid];
    __syncthreads();
    const int warp = tid >> 5, lane = tid & 31;
    for (int s = warp; s < SS; s += 8) {
        float p = 0.f;
        const float* hb = g_hs[0] + (size_t)s * HH * BB + b;
#pragma unroll 8
        for (int j = lane; j < HH; j += 32) p += hb[j * BB] * was[j];
#pragma unroll
        for (int off = 16; off; off >>= 1) p += __shfl_xor_sync(0xffffffffu, p, off);
        if (lane == 0) Es[s] = p;
    }
    __syncthreads();
    float v = (tid < SS) ? Es[tid] : -3.4e38f;
    red[tid] = v;
    __syncthreads();
    for (int off = 128; off; off >>= 1) {
        if (tid < off) red[tid] = fmaxf(red[tid], red[tid + off]);
        __syncthreads();
    }
    const float mx = red[0];
    __syncthreads();
    float e = (tid < SS) ? __expf(Es[tid] - mx) : 0.f;
    red[tid] = e;
    __syncthreads();
    for (int off = 128; off; off >>= 1) {
        if (tid < off) red[tid] += red[tid + off];
        __syncthreads();
    }
    const float sum = red[0];
    if (tid < SS) g_alpha[b * SS + tid] = e / sum;
}

// ---------------- Beta: tanh(Wb @ out2_s^T), per s.  M=256(d) N=128(b) K=256(h) ----------------
__global__ __launch_bounds__(256) void beta_gemm(const float* __restrict__ Wb) {
    const int s  = blockIdx.z;
    const int d0 = blockIdx.y * 128;
    const int n0 = blockIdx.x * 64;
    __shared__ __align__(16) float As[16][128];
    __shared__ __align__(16) float Bs[16][64];
    const int tid = threadIdx.x;
    const int a_m = tid >> 1, a_k = (tid & 1) * 8;
    const int b_k = tid >> 4, b_n = (tid & 15) * 4;
    const int tx = tid & 15, ty = tid >> 4;
    float acc[8][4];
#pragma unroll
    for (int i = 0; i < 8; ++i)
#pragma unroll
        for (int jx = 0; jx < 4; ++jx) acc[i][jx] = 0.0f;

    const float* Ap = Wb + (size_t)(d0 + a_m) * HH + a_k;
    const float* Bp = g_hs[1] + (size_t)s * HH * BB + b_k * BB + n0 + b_n;

    for (int k0 = 0; k0 < HH; k0 += 16) {
        float4 av0 = *(const float4*)(Ap + k0);
        float4 av1 = *(const float4*)(Ap + k0 + 4);
        float4 bv  = *(const float4*)(Bp + (size_t)k0 * BB);
        __syncthreads();
        As[a_k + 0][a_m] = av0.x; As[a_k + 1][a_m] = av0.y;
        As[a_k + 2][a_m] = av0.z; As[a_k + 3][a_m] = av0.w;
        As[a_k + 4][a_m] = av1.x; As[a_k + 5][a_m] = av1.y;
        As[a_k + 6][a_m] = av1.z; As[a_k + 7][a_m] = av1.w;
        *(float4*)&Bs[b_k][b_n] = bv;
        __syncthreads();
#pragma unroll
        for (int k = 0; k < 16; ++k) {
            float a[8], bq[4];
            *(float4*)&a[0] = *(const float4*)&As[k][ty * 8];
            *(float4*)&a[4] = *(const float4*)&As[k][ty * 8 + 4];
            *(float4*)&bq[0] = *(const float4*)&Bs[k][tx * 4];
#pragma unroll
            for (int i = 0; i < 8; ++i)
#pragma unroll
                for (int jx = 0; jx < 4; ++jx) acc[i][jx] += a[i] * bq[jx];
        }
    }
#pragma unroll
    for (int i = 0; i < 8; ++i) {
        int d = d0 + ty * 8 + i;
        float4 v = make_float4(tanhf(acc[i][0]), tanhf(acc[i][1]),
                               tanhf(acc[i][2]), tanhf(acc[i][3]));
        *(float4*)&g_beta[((size_t)s * DD + d) * BB + n0 + tx * 4] = v;
    }
}

// ---------------- ctx[b][d] = sum_s embedded[b][s][d] * beta[s][d][b] * alpha[b][s] ----------------
__global__ __launch_bounds__(128) void ctx_kernel() {
    const int d = blockIdx.x;
    const int b = threadIdx.x;
    float acc = 0.f;
    const float* em = g_embedded + (size_t)b * (SS * DD) + d;
    const float* bt = g_beta + (size_t)d * BB + b;
    const float* al = g_alpha + b * SS;
    for (int s = 0; s < SS; ++s)
        acc += em[(size_t)s * DD] * bt[(size_t)s * DD * BB] * al[s];
    g_ctx[b * DD + d] = acc;
}

// ---------------- out = ctx @ Wout^T ----------------
__global__ __launch_bounds__(128) void out_kernel(const float* __restrict__ Wout,
                                                  float* __restrict__ out) {
    const int b = blockIdx.x;
    const int n = threadIdx.x;
    __shared__ float cs[256];
    cs[n] = g_ctx[b * DD + n];
    cs[n + 128] = g_ctx[b * DD + n + 128];
    __syncthreads();
    float acc = 0.f;
    const float4* wp = (const float4*)(Wout + (size_t)n * DD);
#pragma unroll 8
    for (int d4 = 0; d4 < 64; ++d4) {
        float4 w = wp[d4];
        acc += cs[4 * d4] * w.x + cs[4 * d4 + 1] * w.y +
               cs[4 * d4 + 2] * w.z + cs[4 * d4 + 3] * w.w;
    }
    out[b * NC + n] = acc;
}

// ---------------- launch ----------------
extern "C" void kernel_launch(void* const* d_in, const int* in_sizes, int n_in,
                              void* d_out, int out_size) {
    (void)in_sizes; (void)n_in; (void)out_size;
    const float* inputs  = (const float*)d_in[0];
    const float* tstamp  = (const float*)d_in[1];
    const float* emb     = (const float*)d_in[2];
    const float* Wall1_w = (const float*)d_in[3];
    const float* Wall1_b = (const float*)d_in[4];
    const float* Uall1_w = (const float*)d_in[5];
    const float* Uall1_b = (const float*)d_in[6];
    const float* Wd1_w   = (const float*)d_in[7];
    const float* Wd1_b   = (const float*)d_in[8];
    const float* Wall2_w = (const float*)d_in[9];
    const float* Wall2_b = (const float*)d_in[10];
    const float* Uall2_w = (const float*)d_in[11];
    const float* Uall2_b = (const float*)d_in[12];
    const float* Wd2_w   = (const float*)d_in[13];
    const float* Wd2_b   = (const float*)d_in[14];
    const float* wa_w    = (const float*)d_in[15];
    const float* Wb_w    = (const float*)d_in[16];
    const float* Wout_w  = (const float*)d_in[17];
    const float* h01     = (const float*)d_in[18];
    const float* c01     = (const float*)d_in[19];
    const float* h02     = (const float*)d_in[20];
    const float* c02     = (const float*)d_in[21];
    float* out = (float*)d_out;

    init_kernel<<<128, 256>>>(h01, c01, h02, c02, tstamp);
    embed_gemm<<<dim3(4, 200), 256>>>(inputs, emb);
    ux_gemm<<<dim3(2, 8, 2 * SS), 256>>>(Uall1_w, Uall1_b, Wall1_b,
                                         Uall2_w, Uall2_b, Wall2_b);
    for (int t = 0; t < SS; ++t) {
        step_kernel<<<128, 256>>>(Wall1_w, Wd1_w, Wd1_b,
                                  Wall2_w, Wd2_w, Wd2_b, t);
    }
    alpha_kernel<<<128, 256>>>(wa_w);
    beta_gemm<<<dim3(2, 2, SS), 256>>>(Wb_w);
    ctx_kernel<<<256, 128>>>();
    out_kernel<<<128, 128>>>(Wout_w, out);
}

// round 13
// speedup vs baseline: 1.5871x; 1.5871x over previous
#include <cuda_runtime.h>
#include <cstdint>
#include <cstddef>

// Problem dims
#define BB   128      // batch
#define SS   200      // seq
#define VV   1400     // vocab
#define DD   256      // input/hidden dim
#define HH   256
#define G4   1024     // 4*H
#define NC   128      // classes

// ---------------- packed fp32 (f32x2 / SASS FFMA2) helpers ----------------
#define FMA2(acc, a, b) \
    asm("fma.rn.f32x2 %0, %1, %2, %0;" : "+l"(acc) : "l"(a), "l"(b))
#define DUP2(out, f) \
    do { unsigned int _u = __float_as_uint(f); \
         asm("mov.b64 %0, {%1, %1};" : "=l"(out) : "r"(_u)); } while (0)
__device__ __forceinline__ float lo2(unsigned long long v) {
    return __uint_as_float((unsigned int)v);
}
__device__ __forceinline__ float hi2(unsigned long long v) {
    return __uint_as_float((unsigned int)(v >> 32));
}

// ---------------- device scratch (static, no allocs) ----------------
__device__ __align__(16) float g_embedded[BB * SS * DD];   // [b][s][d]
__device__ __align__(16) float g_ux[2][SS * G4 * BB];      // [l][s][e][b]
__device__ __align__(16) float g_hs[2][SS * HH * BB];      // [l][t][j][b]
// state in k-pair-interleaved layout: element (k,b) at (k>>1)*256 + b*2 + (k&1)
__device__ __align__(16) float g_hbuf[2][2][HH * BB];      // [phase][l][...]
__device__ __align__(16) float g_cbuf[2][2][HH * BB];
__device__ __align__(16) float g_tsT[SS * BB];             // [t][b]
__device__ __align__(16) float g_alpha[BB * SS];
__device__ __align__(16) float g_beta[SS * DD * BB];       // [s][d][b]
__device__ __align__(16) float g_ctx[BB * DD];

// ---------------- helpers ----------------
__device__ __forceinline__ float sigf(float x) { return 1.0f / (1.0f + __expf(-x)); }

// ---------------- init: state transpose (to packed layout), ts transpose ----------------
__global__ void init_kernel(const float* __restrict__ h01, const float* __restrict__ c01,
                            const float* __restrict__ h02, const float* __restrict__ c02,
                            const float* __restrict__ tsp) {
    int gid = blockIdx.x * blockDim.x + threadIdx.x;
    int stride = gridDim.x * blockDim.x;
    for (int i = gid; i < HH * BB; i += stride) {
        int k = i >> 7, b = i & 127;
        int dst = (k >> 1) * 256 + b * 2 + (k & 1);
        g_hbuf[0][0][dst] = h01[b * HH + k];
        g_cbuf[0][0][dst] = c01[b * HH + k];
        g_hbuf[0][1][dst] = h02[b * HH + k];
        g_cbuf[0][1][dst] = c02[b * HH + k];
    }
    for (int i = gid; i < SS * BB; i += stride) {
        int t = i >> 7, b = i & 127;
        g_tsT[i] = tsp[b * SS + t];
    }
}

// ---------------- K1: embedded = inputs @ emb ----------------
// C[M=25600][256] = A[M][1400] * W[1400][256].  BM=128 BN=64 BK=8, 8x4 microtile (f32x2)
__global__ __launch_bounds__(256) void embed_gemm(const float* __restrict__ A,
                                                  const float* __restrict__ W) {
    const int m0 = blockIdx.y * 128;
    const int n0 = blockIdx.x * 64;
    __shared__ __align__(16) float As[8][128];
    __shared__ __align__(16) float Bs[8][64];
    const int tid = threadIdx.x;
    const int a_m = tid >> 1, a_k = (tid & 1) * 4;
    const int b_k = tid >> 5, b_n = (tid & 31) * 2;
    const int tx = tid & 15, ty = tid >> 4;
    unsigned long long accp[4][4];
#pragma unroll
    for (int ip = 0; ip < 4; ++ip)
#pragma unroll
        for (int jx = 0; jx < 4; ++jx) accp[ip][jx] = 0ULL;

    const float* Ap = A + (size_t)(m0 + a_m) * VV + a_k;
    const float* Bp = W + (size_t)b_k * DD + n0 + b_n;

    for (int k0 = 0; k0 < VV; k0 += 8) {
        float4 av = *(const float4*)(Ap + k0);
        float2 bv = *(const float2*)(Bp + (size_t)k0 * DD);
        __syncthreads();
        As[a_k + 0][a_m] = av.x; As[a_k + 1][a_m] = av.y;
        As[a_k + 2][a_m] = av.z; As[a_k + 3][a_m] = av.w;
        Bs[b_k][b_n] = bv.x; Bs[b_k][b_n + 1] = bv.y;
        __syncthreads();
#pragma unroll
        for (int k = 0; k < 8; ++k) {
            const unsigned long long* ap = (const unsigned long long*)&As[k][ty * 8];
            const float* bqf = &Bs[k][tx * 4];
            unsigned long long b2[4];
            DUP2(b2[0], bqf[0]); DUP2(b2[1], bqf[1]);
            DUP2(b2[2], bqf[2]); DUP2(b2[3], bqf[3]);
#pragma unroll
            for (int ip = 0; ip < 4; ++ip) {
                unsigned long long a2 = ap[ip];
#pragma unroll
                for (int jx = 0; jx < 4; ++jx) FMA2(accp[ip][jx], a2, b2[jx]);
            }
        }
    }
#pragma unroll
    for (int ip = 0; ip < 4; ++ip) {
        float4 v0 = make_float4(lo2(accp[ip][0]), lo2(accp[ip][1]),
                                lo2(accp[ip][2]), lo2(accp[ip][3]));
        float4 v1 = make_float4(hi2(accp[ip][0]), hi2(accp[ip][1]),
                                hi2(accp[ip][2]), hi2(accp[ip][3]));
        int m = m0 + ty * 8 + 2 * ip;
        *(float4*)&g_embedded[(size_t)m * DD + n0 + tx * 4] = v0;
        *(float4*)&g_embedded[(size_t)(m + 1) * DD + n0 + tx * 4] = v1;
    }
}

// ---------------- K2: ux[l][s][e][b] = U_l @ embedded_s^T + (Uall_b + Wall_b) ----------------
// per (l,s): M=1024(e) N=128(b) K=256(d).  BM=128 BN=64 BK=16 (f32x2)
__global__ __launch_bounds__(256) void ux_gemm(
    const float* __restrict__ U1, const float* __restrict__ Ub1, const float* __restrict__ Wb1,
    const float* __restrict__ U2, const float* __restrict__ Ub2, const float* __restrict__ Wb2) {
    const int l = blockIdx.z / SS;
    const int s = blockIdx.z % SS;
    const float* U  = l ? U2  : U1;
    const float* bu = l ? Ub2 : Ub1;
    const float* bw = l ? Wb2 : Wb1;
    const int e0 = blockIdx.y * 128;
    const int n0 = blockIdx.x * 64;
    __shared__ __align__(16) float As[16][128];
    __shared__ __align__(16) float Bs[16][64];
    const int tid = threadIdx.x;
    const int a_m = tid >> 1, a_k = (tid & 1) * 8;
    const int b_n = tid >> 2, b_k = (tid & 3) * 4;
    const int tx = tid & 15, ty = tid >> 4;
    unsigned long long accp[4][4];
#pragma unroll
    for (int ip = 0; ip < 4; ++ip)
#pragma unroll
        for (int jx = 0; jx < 4; ++jx) accp[ip][jx] = 0ULL;

    const float* Ap = U + (size_t)(e0 + a_m) * DD + a_k;
    const float* Bp = g_embedded + (size_t)(n0 + b_n) * (SS * DD) + s * DD + b_k;

    for (int k0 = 0; k0 < DD; k0 += 16) {
        float4 av0 = *(const float4*)(Ap + k0);
        float4 av1 = *(const float4*)(Ap + k0 + 4);
        float4 bv  = *(const float4*)(Bp + k0);
        __syncthreads();
        As[a_k + 0][a_m] = av0.x; As[a_k + 1][a_m] = av0.y;
        As[a_k + 2][a_m] = av0.z; As[a_k + 3][a_m] = av0.w;
        As[a_k + 4][a_m] = av1.x; As[a_k + 5][a_m] = av1.y;
        As[a_k + 6][a_m] = av1.z; As[a_k + 7][a_m] = av1.w;
        Bs[b_k + 0][b_n] = bv.x; Bs[b_k + 1][b_n] = bv.y;
        Bs[b_k + 2][b_n] = bv.z; Bs[b_k + 3][b_n] = bv.w;
        __syncthreads();
#pragma unroll
        for (int k = 0; k < 16; ++k) {
            const unsigned long long* ap = (const unsigned long long*)&As[k][ty * 8];
            const float* bqf = &Bs[k][tx * 4];
            unsigned long long b2[4];
            DUP2(b2[0], bqf[0]); DUP2(b2[1], bqf[1]);
            DUP2(b2[2], bqf[2]); DUP2(b2[3], bqf[3]);
#pragma unroll
            for (int ip = 0; ip < 4; ++ip) {
                unsigned long long a2 = ap[ip];
#pragma unroll
                for (int jx = 0; jx < 4; ++jx) FMA2(accp[ip][jx], a2, b2[jx]);
            }
        }
    }
    float* uxl = g_ux[l];
#pragma unroll
    for (int ip = 0; ip < 4; ++ip) {
        int e = e0 + ty * 8 + 2 * ip;
        float bias0 = bu[e] + bw[e];
        float bias1 = bu[e + 1] + bw[e + 1];
        float4 v0 = make_float4(lo2(accp[ip][0]) + bias0, lo2(accp[ip][1]) + bias0,
                                lo2(accp[ip][2]) + bias0, lo2(accp[ip][3]) + bias0);
        float4 v1 = make_float4(hi2(accp[ip][0]) + bias1, hi2(accp[ip][1]) + bias1,
                                hi2(accp[ip][2]) + bias1, hi2(accp[ip][3]) + bias1);
        *(float4*)&uxl[((size_t)s * G4 + e) * BB + n0 + tx * 4] = v0;
        *(float4*)&uxl[((size_t)s * G4 + e + 1) * BB + n0 + tx * 4] = v1;
    }
}

// ---------------- one recurrence step (both LSTMs), f32x2 + k-split 2 ----------------
// 128 blocks: l = blk>>6, unit group j0 = (blk&63)*4.
// 512 threads: ks = tid>>8 (k-half), jj = (tid>>6)&3 (unit), r0 = (tid&63)*2 (batch pair).
__global__ __launch_bounds__(512) void step_kernel(
    const float* __restrict__ Wall1, const float* __restrict__ Wd1w, const float* __restrict__ Wd1b,
    const float* __restrict__ Wall2, const float* __restrict__ Wd2w, const float* __restrict__ Wd2b,
    int t) {
    const int l  = blockIdx.x >> 6;
    const int j0 = (blockIdx.x & 63) * 4;
    const float* Wall = l ? Wall2 : Wall1;
    const float* Wd   = l ? Wd2w : Wd1w;
    const float* Wdb  = l ? Wd2b : Wd1b;

    __shared__ __align__(16) float ws[4][4][256];   // [gate][unit][k]  16 KB
    __shared__ __align__(16) float wds[4][256];     // [unit][k]         4 KB
    __shared__ float bds[4];
    __shared__ float red[256][10];                  // ks=1 partials    10 KB

    const int tid = threadIdx.x;
    // stage weights: 1280 float4 across 512 threads
    for (int idx = tid; idx < 1280; idx += 512) {
        if (idx < 1024) {
            int g = idx >> 8, jj = (idx >> 6) & 3, k4 = idx & 63;
            *(float4*)&ws[g][jj][k4 * 4] =
                *(const float4*)&Wall[((size_t)((g << 8) + j0 + jj)) * DD + k4 * 4];
        } else {
            int j2 = idx - 1024;
            int jj = j2 >> 6, k4 = j2 & 63;
            *(float4*)&wds[jj][k4 * 4] =
                *(const float4*)&Wd[(size_t)(j0 + jj) * DD + k4 * 4];
        }
    }
    if (tid < 4) bds[tid] = Wdb[j0 + tid];
    __syncthreads();

    const int ks = tid >> 8;             // 0/1: k-half
    const int jj = (tid >> 6) & 3;       // unit within group
    const int j  = j0 + jj;
    const int r0 = (tid & 63) * 2;       // batch pair
    const int kp0 = ks * 64;             // k-pair base (k-pair = 2 k values)

    const unsigned long long* wF = (const unsigned long long*)&ws[0][jj][0];
    const unsigned long long* wI = (const unsigned long long*)&ws[1][jj][0];
    const unsigned long long* wO = (const unsigned long long*)&ws[2][jj][0];
    const unsigned long long* wC = (const unsigned long long*)&ws[3][jj][0];
    const unsigned long long* wD = (const unsigned long long*)&wds[jj][0];

    const int pb = t & 1;
    const float* hp = g_hbuf[pb][l];
    const float* cp = g_cbuf[pb][l];
    float* hw = g_hbuf[pb ^ 1][l];
    float* cw = g_cbuf[pb ^ 1][l];

    // packed accumulators: lanes = (even-k partial, odd-k partial)
    unsigned long long aF0 = 0, aF1 = 0, aI0 = 0, aI1 = 0, aO0 = 0;
    unsigned long long aO1 = 0, aC0 = 0, aC1 = 0, aD0 = 0, aD1 = 0;

#pragma unroll 8
    for (int kp = 0; kp < 64; ++kp) {
        const int kk = kp0 + kp;
        // state layout: (k,b) at (k>>1)*256 + b*2 + (k&1)
        // one LDG.128 = (h[2kk][r0], h[2kk+1][r0], h[2kk][r0+1], h[2kk+1][r0+1])
        ulonglong2 h2 = *(const ulonglong2*)(hp + kk * 256 + r0 * 2);
        ulonglong2 c2 = *(const ulonglong2*)(cp + kk * 256 + r0 * 2);
        unsigned long long wf2 = wF[kk], wi2 = wI[kk], wo2 = wO[kk];
        unsigned long long wc2 = wC[kk], wd2 = wD[kk];
        FMA2(aF0, h2.x, wf2); FMA2(aF1, h2.y, wf2);
        FMA2(aI0, h2.x, wi2); FMA2(aI1, h2.y, wi2);
        FMA2(aO0, h2.x, wo2); FMA2(aO1, h2.y, wo2);
        FMA2(aC0, h2.x, wc2); FMA2(aC1, h2.y, wc2);
        FMA2(aD0, c2.x, wd2); FMA2(aD1, c2.y, wd2);
    }

    // collapse packed lanes
    float sF0 = lo2(aF0) + hi2(aF0), sF1 = lo2(aF1) + hi2(aF1);
    float sI0 = lo2(aI0) + hi2(aI0), sI1 = lo2(aI1) + hi2(aI1);
    float sO0 = lo2(aO0) + hi2(aO0), sO1 = lo2(aO1) + hi2(aO1);
    float sC0 = lo2(aC0) + hi2(aC0), sC1 = lo2(aC1) + hi2(aC1);
    float sD0 = lo2(aD0) + hi2(aD0), sD1 = lo2(aD1) + hi2(aD1);

    const int idx = tid & 255;
    if (ks == 1) {
        red[idx][0] = sF0; red[idx][1] = sF1;
        red[idx][2] = sI0; red[idx][3] = sI1;
        red[idx][4] = sO0; red[idx][5] = sO1;
        red[idx][6] = sC0; red[idx][7] = sC1;
        red[idx][8] = sD0; red[idx][9] = sD1;
    }
    __syncthreads();
    if (ks == 0) {
        sF0 += red[idx][0]; sF1 += red[idx][1];
        sI0 += red[idx][2]; sI1 += red[idx][3];
        sO0 += red[idx][4]; sO1 += red[idx][5];
        sC0 += red[idx][6]; sC1 += red[idx][7];
        sD0 += red[idx][8]; sD1 += red[idx][9];

        const float bd = bds[jj];
        const float* uxp = g_ux[l] + ((size_t)t * G4 + j) * BB + r0;
        float2 uf = __ldcs((const float2*)(uxp + 0 * 256 * BB));
        float2 ui = __ldcs((const float2*)(uxp + 1 * 256 * BB));
        float2 uo = __ldcs((const float2*)(uxp + 2 * 256 * BB));
        float2 uc = __ldcs((const float2*)(uxp + 3 * 256 * BB));
        float2 ts2 = *(const float2*)(g_tsT + t * BB + r0);
        const int cbase = (j >> 1) * 256 + r0 * 2 + (j & 1);
        float co0 = cp[cbase], co1 = cp[cbase + 2];

        float csx0 = tanhf(sD0 + bd), csx1 = tanhf(sD1 + bd);
        float ca0 = co0 + csx0 * (ts2.x - 1.0f);
        float ca1 = co1 + csx1 * (ts2.y - 1.0f);
        float f0 = sigf(sF0 + uf.x), f1 = sigf(sF1 + uf.y);
        float i0 = sigf(sI0 + ui.x), i1 = sigf(sI1 + ui.y);
        float o0 = sigf(sO0 + uo.x), o1 = sigf(sO1 + uo.y);
        float q0 = sigf(sC0 + uc.x), q1 = sigf(sC1 + uc.y);
        float cn0 = f0 * ca0 + i0 * q0, cn1 = f1 * ca1 + i1 * q1;
        float hn0 = o0 * tanhf(cn0),    hn1 = o1 * tanhf(cn1);

        cw[cbase] = cn0; cw[cbase + 2] = cn1;
        hw[cbase] = hn0; hw[cbase + 2] = hn1;
        *(float2*)(g_hs[l] + ((size_t)t * HH + j) * BB + r0) = make_float2(hn0, hn1);
    }
}

// ---------------- alpha: E = out1 . wa ; softmax over seq ----------------
__global__ __launch_bounds__(256) void alpha_kernel(const float* __restrict__ wa) {
    const int b = blockIdx.x;
    __shared__ float was[256];
    __shared__ float Es[224];
    __shared__ float red[256];
    const int tid = threadIdx.x;
    was[tid] = wa[tid];
    __syncthreads();
    const int warp = tid >> 5, lane = tid & 31;
    for (int s = warp; s < SS; s += 8) {
        float p = 0.f;
        const float* hb = g_hs[0] + (size_t)s * HH * BB + b;
#pragma unroll 8
        for (int j = lane; j < HH; j += 32) p += hb[j * BB] * was[j];
#pragma unroll
        for (int off = 16; off; off >>= 1) p += __shfl_xor_sync(0xffffffffu, p, off);
        if (lane == 0) Es[s] = p;
    }
    __syncthreads();
    float v = (tid < SS) ? Es[tid] : -3.4e38f;
    red[tid] = v;
    __syncthreads();
    for (int off = 128; off; off >>= 1) {
        if (tid < off) red[tid] = fmaxf(red[tid], red[tid + off]);
        __syncthreads();
    }
    const float mx = red[0];
    __syncthreads();
    float e = (tid < SS) ? __expf(Es[tid] - mx) : 0.f;
    red[tid] = e;
    __syncthreads();
    for (int off = 128; off; off >>= 1) {
        if (tid < off) red[tid] += red[tid + off];
        __syncthreads();
    }
    const float sum = red[0];
    if (tid < SS) g_alpha[b * SS + tid] = e / sum;
}

// ---------------- Beta: tanh(Wb @ out2_s^T), per s.  M=256(d) N=128(b) K=256(h) ----------------
__global__ __launch_bounds__(256) void beta_gemm(const float* __restrict__ Wb) {
    const int s  = blockIdx.z;
    const int d0 = blockIdx.y * 128;
    const int n0 = blockIdx.x * 64;
    __shared__ __align__(16) float As[16][128];
    __shared__ __align__(16) float Bs[16][64];
    const int tid = threadIdx.x;
    const int a_m = tid >> 1, a_k = (tid & 1) * 8;
    const int b_k = tid >> 4, b_n = (tid & 15) * 4;
    const int tx = tid & 15, ty = tid >> 4;
    unsigned long long accp[4][4];
#pragma unroll
    for (int ip = 0; ip < 4; ++ip)
#pragma unroll
        for (int jx = 0; jx < 4; ++jx) accp[ip][jx] = 0ULL;

    const float* Ap = Wb + (size_t)(d0 + a_m) * HH + a_k;
    const float* Bp = g_hs[1] + (size_t)s * HH * BB + b_k * BB + n0 + b_n;

    for (int k0 = 0; k0 < HH; k0 += 16) {
        float4 av0 = *(const float4*)(Ap + k0);
        float4 av1 = *(const float4*)(Ap + k0 + 4);
        float4 bv  = *(const float4*)(Bp + (size_t)k0 * BB);
        __syncthreads();
        As[a_k + 0][a_m] = av0.x; As[a_k + 1][a_m] = av0.y;
        As[a_k + 2][a_m] = av0.z; As[a_k + 3][a_m] = av0.w;
        As[a_k + 4][a_m] = av1.x; As[a_k + 5][a_m] = av1.y;
        As[a_k + 6][a_m] = av1.z; As[a_k + 7][a_m] = av1.w;
        *(float4*)&Bs[b_k][b_n] = bv;
        __syncthreads();
#pragma unroll
        for (int k = 0; k < 16; ++k) {
            const unsigned long long* ap = (const unsigned long long*)&As[k][ty * 8];
            const float* bqf = &Bs[k][tx * 4];
            unsigned long long b2[4];
            DUP2(b2[0], bqf[0]); DUP2(b2[1], bqf[1]);
            DUP2(b2[2], bqf[2]); DUP2(b2[3], bqf[3]);
#pragma unroll
            for (int ip = 0; ip < 4; ++ip) {
                unsigned long long a2 = ap[ip];
#pragma unroll
                for (int jx = 0; jx < 4; ++jx) FMA2(accp[ip][jx], a2, b2[jx]);
            }
        }
    }
#pragma unroll
    for (int ip = 0; ip < 4; ++ip) {
        int d = d0 + ty * 8 + 2 * ip;
        float4 v0 = make_float4(tanhf(lo2(accp[ip][0])), tanhf(lo2(accp[ip][1])),
                                tanhf(lo2(accp[ip][2])), tanhf(lo2(accp[ip][3])));
        float4 v1 = make_float4(tanhf(hi2(accp[ip][0])), tanhf(hi2(accp[ip][1])),
                                tanhf(hi2(accp[ip][2])), tanhf(hi2(accp[ip][3])));
        *(float4*)&g_beta[((size_t)s * DD + d) * BB + n0 + tx * 4] = v0;
        *(float4*)&g_beta[((size_t)s * DD + d + 1) * BB + n0 + tx * 4] = v1;
    }
}

// ---------------- ctx[b][d] = sum_s embedded[b][s][d] * beta[s][d][b] * alpha[b][s] ----------------
__global__ __launch_bounds__(128) void ctx_kernel() {
    const int d = blockIdx.x;
    const int b = threadIdx.x;
    float acc = 0.f;
    const float* em = g_embedded + (size_t)b * (SS * DD) + d;
    const float* bt = g_beta + (size_t)d * BB + b;
    const float* al = g_alpha + b * SS;
    for (int s = 0; s < SS; ++s)
        acc += em[(size_t)s * DD] * bt[(size_t)s * DD * BB] * al[s];
    g_ctx[b * DD + d] = acc;
}

// ---------------- out = ctx @ Wout^T ----------------
__global__ __launch_bounds__(128) void out_kernel(const float* __restrict__ Wout,
                                                  float* __restrict__ out) {
    const int b = blockIdx.x;
    const int n = threadIdx.x;
    __shared__ float cs[256];
    cs[n] = g_ctx[b * DD + n];
    cs[n + 128] = g_ctx[b * DD + n + 128];
    __syncthreads();
    float acc = 0.f;
    const float4* wp = (const float4*)(Wout + (size_t)n * DD);
#pragma unroll 8
    for (int d4 = 0; d4 < 64; ++d4) {
        float4 w = wp[d4];
        acc += cs[4 * d4] * w.x + cs[4 * d4 + 1] * w.y +
               cs[4 * d4 + 2] * w.z + cs[4 * d4 + 3] * w.w;
    }
    out[b * NC + n] = acc;
}

// ---------------- launch ----------------
extern "C" void kernel_launch(void* const* d_in, const int* in_sizes, int n_in,
                              void* d_out, int out_size) {
    (void)in_sizes; (void)n_in; (void)out_size;
    const float* inputs  = (const float*)d_in[0];
    const float* tstamp  = (const float*)d_in[1];
    const float* emb     = (const float*)d_in[2];
    const float* Wall1_w = (const float*)d_in[3];
    const float* Wall1_b = (const float*)d_in[4];
    const float* Uall1_w = (const float*)d_in[5];
    const float* Uall1_b = (const float*)d_in[6];
    const float* Wd1_w   = (const float*)d_in[7];
    const float* Wd1_b   = (const float*)d_in[8];
    const float* Wall2_w = (const float*)d_in[9];
    const float* Wall2_b = (const float*)d_in[10];
    const float* Uall2_w = (const float*)d_in[11];
    const float* Uall2_b = (const float*)d_in[12];
    const float* Wd2_w   = (const float*)d_in[13];
    const float* Wd2_b   = (const float*)d_in[14];
    const float* wa_w    = (const float*)d_in[15];
    const float* Wb_w    = (const float*)d_in[16];
    const float* Wout_w  = (const float*)d_in[17];
    const float* h01     = (const float*)d_in[18];
    const float* c01     = (const float*)d_in[19];
    const float* h02     = (const float*)d_in[20];
    const float* c02     = (const float*)d_in[21];
    float* out = (float*)d_out;

    init_kernel<<<128, 256>>>(h01, c01, h02, c02, tstamp);
    embed_gemm<<<dim3(4, 200), 256>>>(inputs, emb);
    ux_gemm<<<dim3(2, 8, 2 * SS), 256>>>(Uall1_w, Uall1_b, Wall1_b,
                                         Uall2_w, Uall2_b, Wall2_b);
    for (int t = 0; t < SS; ++t) {
        step_kernel<<<128, 512>>>(Wall1_w, Wd1_w, Wd1_b,
                                  Wall2_w, Wd2_w, Wd2_b, t);
    }
    alpha_kernel<<<128, 256>>>(wa_w);
    beta_gemm<<<dim3(2, 2, SS), 256>>>(Wb_w);
    ctx_kernel<<<256, 128>>>();
    out_kernel<<<128, 128>>>(Wout_w, out);
}

// round 14
// speedup vs baseline: 1.9666x; 1.2391x over previous
#include <cuda_runtime.h>
#include <cstdint>
#include <cstddef>

// Problem dims
#define BB   128      // batch
#define SS   200      // seq
#define VV   1400     // vocab
#define DD   256      // input/hidden dim
#define HH   256
#define G4   1024     // 4*H
#define NC   128      // classes

#define NBLK 128      // recurrence grid (co-resident, cooperative launch)

// ---------------- packed fp32 (f32x2 / SASS FFMA2) helpers ----------------
#define FMA2(acc, a, b) \
    asm("fma.rn.f32x2 %0, %1, %2, %0;" : "+l"(acc) : "l"(a), "l"(b))
#define DUP2(out, f) \
    do { unsigned int _u = __float_as_uint(f); \
         asm("mov.b64 %0, {%1, %1};" : "=l"(out) : "r"(_u)); } while (0)
__device__ __forceinline__ float lo2(unsigned long long v) {
    return __uint_as_float((unsigned int)v);
}
__device__ __forceinline__ float hi2(unsigned long long v) {
    return __uint_as_float((unsigned int)(v >> 32));
}

// ---------------- device scratch (static, no allocs) ----------------
__device__ __align__(16) float g_embedded[BB * SS * DD];   // [b][s][d]
__device__ __align__(16) float g_ux[2][SS * G4 * BB];      // [l][s][e][b]
__device__ __align__(16) float g_hs[2][SS * HH * BB];      // [l][t][j][b]
// state in k-pair-interleaved layout: element (k,b) at (k>>1)*256 + b*2 + (k&1)
__device__ __align__(16) float g_hbuf[2][2][HH * BB];      // [phase][l][...]
__device__ __align__(16) float g_cbuf[2][2][HH * BB];
__device__ __align__(16) float g_tsT[SS * BB];             // [t][b]
__device__ __align__(16) float g_alpha[BB * SS];
__device__ __align__(16) float g_beta[SS * DD * BB];       // [s][d][b]
__device__ __align__(16) float g_ctx[BB * DD];
__device__ unsigned g_bar_count;
__device__ unsigned g_bar_phase;

// ---------------- helpers ----------------
__device__ __forceinline__ float sigf(float x) { return 1.0f / (1.0f + __expf(-x)); }

// grid barrier for NBLK co-resident blocks (cooperative launch guarantees residency).
// Monotonic phase targets: each target value used exactly once per kernel run.
// Entry __threadfence() by ALL threads: makes each thread's prior STGs visible (L2)
// before this block's arrival is signaled.
__device__ __forceinline__ void gridbar(unsigned target) {
    __threadfence();
    __syncthreads();
    if (threadIdx.x == 0) {
        unsigned old = atomicAdd(&g_bar_count, 1u);
        if (old == NBLK - 1u) {
            atomicExch(&g_bar_count, 0u);
            __threadfence();
            atomicExch(&g_bar_phase, target);
        } else {
            while (atomicAdd(&g_bar_phase, 0u) < target) { __nanosleep(32); }
        }
        __threadfence();
    }
    __syncthreads();
}

// ---------------- init: barrier reset, state transpose (packed layout), ts transpose ----------------
__global__ void init_kernel(const float* __restrict__ h01, const float* __restrict__ c01,
                            const float* __restrict__ h02, const float* __restrict__ c02,
                            const float* __restrict__ tsp) {
    int gid = blockIdx.x * blockDim.x + threadIdx.x;
    int stride = gridDim.x * blockDim.x;
    if (gid == 0) { g_bar_count = 0u; g_bar_phase = 0u; }
    for (int i = gid; i < HH * BB; i += stride) {
        int k = i >> 7, b = i & 127;
        int dst = (k >> 1) * 256 + b * 2 + (k & 1);
        g_hbuf[0][0][dst] = h01[b * HH + k];
        g_cbuf[0][0][dst] = c01[b * HH + k];
        g_hbuf[0][1][dst] = h02[b * HH + k];
        g_cbuf[0][1][dst] = c02[b * HH + k];
    }
    for (int i = gid; i < SS * BB; i += stride) {
        int t = i >> 7, b = i & 127;
        g_tsT[i] = tsp[b * SS + t];
    }
}

// ---------------- K1: embedded = inputs @ emb ----------------
// C[M=25600][256] = A[M][1400] * W[1400][256].  BM=128 BN=64 BK=8, 8x4 microtile (f32x2)
__global__ __launch_bounds__(256) void embed_gemm(const float* __restrict__ A,
                                                  const float* __restrict__ W) {
    const int m0 = blockIdx.y * 128;
    const int n0 = blockIdx.x * 64;
    __shared__ __align__(16) float As[8][128];
    __shared__ __align__(16) float Bs[8][64];
    const int tid = threadIdx.x;
    const int a_m = tid >> 1, a_k = (tid & 1) * 4;
    const int b_k = tid >> 5, b_n = (tid & 31) * 2;
    const int tx = tid & 15, ty = tid >> 4;
    unsigned long long accp[4][4];
#pragma unroll
    for (int ip = 0; ip < 4; ++ip)
#pragma unroll
        for (int jx = 0; jx < 4; ++jx) accp[ip][jx] = 0ULL;

    const float* Ap = A + (size_t)(m0 + a_m) * VV + a_k;
    const float* Bp = W + (size_t)b_k * DD + n0 + b_n;

    for (int k0 = 0; k0 < VV; k0 += 8) {
        float4 av = *(const float4*)(Ap + k0);
        float2 bv = *(const float2*)(Bp + (size_t)k0 * DD);
        __syncthreads();
        As[a_k + 0][a_m] = av.x; As[a_k + 1][a_m] = av.y;
        As[a_k + 2][a_m] = av.z; As[a_k + 3][a_m] = av.w;
        Bs[b_k][b_n] = bv.x; Bs[b_k][b_n + 1] = bv.y;
        __syncthreads();
#pragma unroll
        for (int k = 0; k < 8; ++k) {
            const unsigned long long* ap = (const unsigned long long*)&As[k][ty * 8];
            const float* bqf = &Bs[k][tx * 4];
            unsigned long long b2[4];
            DUP2(b2[0], bqf[0]); DUP2(b2[1], bqf[1]);
            DUP2(b2[2], bqf[2]); DUP2(b2[3], bqf[3]);
#pragma unroll
            for (int ip = 0; ip < 4; ++ip) {
                unsigned long long a2 = ap[ip];
#pragma unroll
                for (int jx = 0; jx < 4; ++jx) FMA2(accp[ip][jx], a2, b2[jx]);
            }
        }
    }
#pragma unroll
    for (int ip = 0; ip < 4; ++ip) {
        float4 v0 = make_float4(lo2(accp[ip][0]), lo2(accp[ip][1]),
                                lo2(accp[ip][2]), lo2(accp[ip][3]));
        float4 v1 = make_float4(hi2(accp[ip][0]), hi2(accp[ip][1]),
                                hi2(accp[ip][2]), hi2(accp[ip][3]));
        int m = m0 + ty * 8 + 2 * ip;
        *(float4*)&g_embedded[(size_t)m * DD + n0 + tx * 4] = v0;
        *(float4*)&g_embedded[(size_t)(m + 1) * DD + n0 + tx * 4] = v1;
    }
}

// ---------------- K2: ux[l][s][e][b] = U_l @ embedded_s^T + (Uall_b + Wall_b) ----------------
// per (l,s): M=1024(e) N=128(b) K=256(d).  BM=128 BN=64 BK=16 (f32x2)
__global__ __launch_bounds__(256) void ux_gemm(
    const float* __restrict__ U1, const float* __restrict__ Ub1, const float* __restrict__ Wb1,
    const float* __restrict__ U2, const float* __restrict__ Ub2, const float* __restrict__ Wb2) {
    const int l = blockIdx.z / SS;
    const int s = blockIdx.z % SS;
    const float* U  = l ? U2  : U1;
    const float* bu = l ? Ub2 : Ub1;
    const float* bw = l ? Wb2 : Wb1;
    const int e0 = blockIdx.y * 128;
    const int n0 = blockIdx.x * 64;
    __shared__ __align__(16) float As[16][128];
    __shared__ __align__(16) float Bs[16][64];
    const int tid = threadIdx.x;
    const int a_m = tid >> 1, a_k = (tid & 1) * 8;
    const int b_n = tid >> 2, b_k = (tid & 3) * 4;
    const int tx = tid & 15, ty = tid >> 4;
    unsigned long long accp[4][4];
#pragma unroll
    for (int ip = 0; ip < 4; ++ip)
#pragma unroll
        for (int jx = 0; jx < 4; ++jx) accp[ip][jx] = 0ULL;

    const float* Ap = U + (size_t)(e0 + a_m) * DD + a_k;
    const float* Bp = g_embedded + (size_t)(n0 + b_n) * (SS * DD) + s * DD + b_k;

    for (int k0 = 0; k0 < DD; k0 += 16) {
        float4 av0 = *(const float4*)(Ap + k0);
        float4 av1 = *(const float4*)(Ap + k0 + 4);
        float4 bv  = *(const float4*)(Bp + k0);
        __syncthreads();
        As[a_k + 0][a_m] = av0.x; As[a_k + 1][a_m] = av0.y;
        As[a_k + 2][a_m] = av0.z; As[a_k + 3][a_m] = av0.w;
        As[a_k + 4][a_m] = av1.x; As[a_k + 5][a_m] = av1.y;
        As[a_k + 6][a_m] = av1.z; As[a_k + 7][a_m] = av1.w;
        Bs[b_k + 0][b_n] = bv.x; Bs[b_k + 1][b_n] = bv.y;
        Bs[b_k + 2][b_n] = bv.z; Bs[b_k + 3][b_n] = bv.w;
        __syncthreads();
#pragma unroll
        for (int k = 0; k < 16; ++k) {
            const unsigned long long* ap = (const unsigned long long*)&As[k][ty * 8];
            const float* bqf = &Bs[k][tx * 4];
            unsigned long long b2[4];
            DUP2(b2[0], bqf[0]); DUP2(b2[1], bqf[1]);
            DUP2(b2[2], bqf[2]); DUP2(b2[3], bqf[3]);
#pragma unroll
            for (int ip = 0; ip < 4; ++ip) {
                unsigned long long a2 = ap[ip];
#pragma unroll
                for (int jx = 0; jx < 4; ++jx) FMA2(accp[ip][jx], a2, b2[jx]);
            }
        }
    }
    float* uxl = g_ux[l];
#pragma unroll
    for (int ip = 0; ip < 4; ++ip) {
        int e = e0 + ty * 8 + 2 * ip;
        float bias0 = bu[e] + bw[e];
        float bias1 = bu[e + 1] + bw[e + 1];
        float4 v0 = make_float4(lo2(accp[ip][0]) + bias0, lo2(accp[ip][1]) + bias0,
                                lo2(accp[ip][2]) + bias0, lo2(accp[ip][3]) + bias0);
        float4 v1 = make_float4(hi2(accp[ip][0]) + bias1, hi2(accp[ip][1]) + bias1,
                                hi2(accp[ip][2]) + bias1, hi2(accp[ip][3]) + bias1);
        *(float4*)&uxl[((size_t)s * G4 + e) * BB + n0 + tx * 4] = v0;
        *(float4*)&uxl[((size_t)s * G4 + e + 1) * BB + n0 + tx * 4] = v1;
    }
}

// ---------------- persistent recurrence (both LSTMs, 200 steps, one launch) ----------------
// Cooperative launch: 128 blocks guaranteed co-resident.
// Block: l = blk>>6, unit group j0 = (blk&63)*4.
// 512 threads: ks = tid>>8 (k-half), jj = (tid>>6)&3 (unit), r0 = (tid&63)*2 (batch pair).
// Weights staged in smem ONCE; state double-buffered, read via __ldcg (L2-coherent).
__global__ __launch_bounds__(512, 1) void recur_kernel(
    const float* __restrict__ Wall1, const float* __restrict__ Wd1w, const float* __restrict__ Wd1b,
    const float* __restrict__ Wall2, const float* __restrict__ Wd2w, const float* __restrict__ Wd2b) {
    const int l  = blockIdx.x >> 6;
    const int j0 = (blockIdx.x & 63) * 4;
    const float* Wall = l ? Wall2 : Wall1;
    const float* Wd   = l ? Wd2w : Wd1w;
    const float* Wdb  = l ? Wd2b : Wd1b;

    __shared__ __align__(16) float ws[4][4][256];   // [gate][unit][k]  16 KB
    __shared__ __align__(16) float wds[4][256];     // [unit][k]         4 KB
    __shared__ float bds[4];
    __shared__ float red[256][10];                  // ks=1 partials    10 KB

    const int tid = threadIdx.x;
    // stage weights once: 1280 float4 across 512 threads
    for (int idx = tid; idx < 1280; idx += 512) {
        if (idx < 1024) {
            int g = idx >> 8, jw = (idx >> 6) & 3, k4 = idx & 63;
            *(float4*)&ws[g][jw][k4 * 4] =
                *(const float4*)&Wall[((size_t)((g << 8) + j0 + jw)) * DD + k4 * 4];
        } else {
            int j2 = idx - 1024;
            int jw = j2 >> 6, k4 = j2 & 63;
            *(float4*)&wds[jw][k4 * 4] =
                *(const float4*)&Wd[(size_t)(j0 + jw) * DD + k4 * 4];
        }
    }
    if (tid < 4) bds[tid] = Wdb[j0 + tid];
    __syncthreads();

    const int ks = tid >> 8;             // 0/1: k-half
    const int jj = (tid >> 6) & 3;       // unit within group
    const int j  = j0 + jj;
    const int r0 = (tid & 63) * 2;       // batch pair
    const int kp0 = ks * 64;             // k-pair base (k-pair = 2 k values)
    const float bd = bds[jj];

    const unsigned long long* wF = (const unsigned long long*)&ws[0][jj][0];
    const unsigned long long* wI = (const unsigned long long*)&ws[1][jj][0];
    const unsigned long long* wO = (const unsigned long long*)&ws[2][jj][0];
    const unsigned long long* wC = (const unsigned long long*)&ws[3][jj][0];
    const unsigned long long* wD = (const unsigned long long*)&wds[jj][0];
    const int idx = tid & 255;
    const int cbase = (j >> 1) * 256 + r0 * 2 + (j & 1);
    float* hs_l = g_hs[l];
    const float* ux_l = g_ux[l];

    for (int t = 0; t < SS; ++t) {
        gridbar((unsigned)(t + 1));      // prev step's state drained to L2

        const int pb = t & 1;
        const float* hp = g_hbuf[pb][l];
        const float* cp = g_cbuf[pb][l];
        float* hw = g_hbuf[pb ^ 1][l];
        float* cw = g_cbuf[pb ^ 1][l];

        // packed accumulators: lanes = (even-k partial, odd-k partial)
        unsigned long long aF0 = 0, aF1 = 0, aI0 = 0, aI1 = 0, aO0 = 0;
        unsigned long long aO1 = 0, aC0 = 0, aC1 = 0, aD0 = 0, aD1 = 0;

#pragma unroll 8
        for (int kp = 0; kp < 64; ++kp) {
            const int kk = kp0 + kp;
            ulonglong2 h2 = __ldcg((const ulonglong2*)(hp + kk * 256 + r0 * 2));
            ulonglong2 c2 = __ldcg((const ulonglong2*)(cp + kk * 256 + r0 * 2));
            unsigned long long wf2 = wF[kk], wi2 = wI[kk], wo2 = wO[kk];
            unsigned long long wc2 = wC[kk], wd2 = wD[kk];
            FMA2(aF0, h2.x, wf2); FMA2(aF1, h2.y, wf2);
            FMA2(aI0, h2.x, wi2); FMA2(aI1, h2.y, wi2);
            FMA2(aO0, h2.x, wo2); FMA2(aO1, h2.y, wo2);
            FMA2(aC0, h2.x, wc2); FMA2(aC1, h2.y, wc2);
            FMA2(aD0, c2.x, wd2); FMA2(aD1, c2.y, wd2);
        }

        // collapse packed lanes
        float sF0 = lo2(aF0) + hi2(aF0), sF1 = lo2(aF1) + hi2(aF1);
        float sI0 = lo2(aI0) + hi2(aI0), sI1 = lo2(aI1) + hi2(aI1);
        float sO0 = lo2(aO0) + hi2(aO0), sO1 = lo2(aO1) + hi2(aO1);
        float sC0 = lo2(aC0) + hi2(aC0), sC1 = lo2(aC1) + hi2(aC1);
        float sD0 = lo2(aD0) + hi2(aD0), sD1 = lo2(aD1) + hi2(aD1);

        if (ks == 1) {
            red[idx][0] = sF0; red[idx][1] = sF1;
            red[idx][2] = sI0; red[idx][3] = sI1;
            red[idx][4] = sO0; red[idx][5] = sO1;
            red[idx][6] = sC0; red[idx][7] = sC1;
            red[idx][8] = sD0; red[idx][9] = sD1;
        }
        __syncthreads();
        if (ks == 0) {
            sF0 += red[idx][0]; sF1 += red[idx][1];
            sI0 += red[idx][2]; sI1 += red[idx][3];
            sO0 += red[idx][4]; sO1 += red[idx][5];
            sC0 += red[idx][6]; sC1 += red[idx][7];
            sD0 += red[idx][8]; sD1 += red[idx][9];

            const float* uxp = ux_l + ((size_t)t * G4 + j) * BB + r0;
            float2 uf = __ldcs((const float2*)(uxp + 0 * 256 * BB));
            float2 ui = __ldcs((const float2*)(uxp + 1 * 256 * BB));
            float2 uo = __ldcs((const float2*)(uxp + 2 * 256 * BB));
            float2 uc = __ldcs((const float2*)(uxp + 3 * 256 * BB));
            float2 ts2 = *(const float2*)(g_tsT + t * BB + r0);
            float co0 = __ldcg(cp + cbase), co1 = __ldcg(cp + cbase + 2);

            float csx0 = tanhf(sD0 + bd), csx1 = tanhf(sD1 + bd);
            float ca0 = co0 + csx0 * (ts2.x - 1.0f);
            float ca1 = co1 + csx1 * (ts2.y - 1.0f);
            float f0 = sigf(sF0 + uf.x), f1 = sigf(sF1 + uf.y);
            float i0 = sigf(sI0 + ui.x), i1 = sigf(sI1 + ui.y);
            float o0 = sigf(sO0 + uo.x), o1 = sigf(sO1 + uo.y);
            float q0 = sigf(sC0 + uc.x), q1 = sigf(sC1 + uc.y);
            float cn0 = f0 * ca0 + i0 * q0, cn1 = f1 * ca1 + i1 * q1;
            float hn0 = o0 * tanhf(cn0),    hn1 = o1 * tanhf(cn1);

            cw[cbase] = cn0; cw[cbase + 2] = cn1;
            hw[cbase] = hn0; hw[cbase + 2] = hn1;
            *(float2*)(hs_l + ((size_t)t * HH + j) * BB + r0) = make_float2(hn0, hn1);
        }
    }
}

// ---------------- alpha: E = out1 . wa ; softmax over seq ----------------
__global__ __launch_bounds__(256) void alpha_kernel(const float* __restrict__ wa) {
    const int b = blockIdx.x;
    __shared__ float was[256];
    __shared__ float Es[224];
    __shared__ float red[256];
    const int tid = threadIdx.x;
    was[tid] = wa[tid];
    __syncthreads();
    const int warp = tid >> 5, lane = tid & 31;
    for (int s = warp; s < SS; s += 8) {
        float p = 0.f;
        const float* hb = g_hs[0] + (size_t)s * HH * BB + b;
#pragma unroll 8
        for (int j = lane; j < HH; j += 32) p += hb[j * BB] * was[j];
#pragma unroll
        for (int off = 16; off; off >>= 1) p += __shfl_xor_sync(0xffffffffu, p, off);
        if (lane == 0) Es[s] = p;
    }
    __syncthreads();
    float v = (tid < SS) ? Es[tid] : -3.4e38f;
    red[tid] = v;
    __syncthreads();
    for (int off = 128; off; off >>= 1) {
        if (tid < off) red[tid] = fmaxf(red[tid], red[tid + off]);
        __syncthreads();
    }
    const float mx = red[0];
    __syncthreads();
    float e = (tid < SS) ? __expf(Es[tid] - mx) : 0.f;
    red[tid] = e;
    __syncthreads();
    for (int off = 128; off; off >>= 1) {
        if (tid < off) red[tid] += red[tid + off];
        __syncthreads();
    }
    const float sum = red[0];
    if (tid < SS) g_alpha[b * SS + tid] = e / sum;
}

// ---------------- Beta: tanh(Wb @ out2_s^T), per s.  M=256(d) N=128(b) K=256(h) ----------------
__global__ __launch_bounds__(256) void beta_gemm(const float* __restrict__ Wb) {
    const int s  = blockIdx.z;
    const int d0 = blockIdx.y * 128;
    const int n0 = blockIdx.x * 64;
    __shared__ __align__(16) float As[16][128];
    __shared__ __align__(16) float Bs[16][64];
    const int tid = threadIdx.x;
    const int a_m = tid >> 1, a_k = (tid & 1) * 8;
    const int b_k = tid >> 4, b_n = (tid & 15) * 4;
    const int tx = tid & 15, ty = tid >> 4;
    unsigned long long accp[4][4];
#pragma unroll
    for (int ip = 0; ip < 4; ++ip)
#pragma unroll
        for (int jx = 0; jx < 4; ++jx) accp[ip][jx] = 0ULL;

    const float* Ap = Wb + (size_t)(d0 + a_m) * HH + a_k;
    const float* Bp = g_hs[1] + (size_t)s * HH * BB + b_k * BB + n0 + b_n;

    for (int k0 = 0; k0 < HH; k0 += 16) {
        float4 av0 = *(const float4*)(Ap + k0);
        float4 av1 = *(const float4*)(Ap + k0 + 4);
        float4 bv  = *(const float4*)(Bp + (size_t)k0 * BB);
        __syncthreads();
        As[a_k + 0][a_m] = av0.x; As[a_k + 1][a_m] = av0.y;
        As[a_k + 2][a_m] = av0.z; As[a_k + 3][a_m] = av0.w;
        As[a_k + 4][a_m] = av1.x; As[a_k + 5][a_m] = av1.y;
        As[a_k + 6][a_m] = av1.z; As[a_k + 7][a_m] = av1.w;
        *(float4*)&Bs[b_k][b_n] = bv;
        __syncthreads();
#pragma unroll
        for (int k = 0; k < 16; ++k) {
            const unsigned long long* ap = (const unsigned long long*)&As[k][ty * 8];
            const float* bqf = &Bs[k][tx * 4];
            unsigned long long b2[4];
            DUP2(b2[0], bqf[0]); DUP2(b2[1], bqf[1]);
            DUP2(b2[2], bqf[2]); DUP2(b2[3], bqf[3]);
#pragma unroll
            for (int ip = 0; ip < 4; ++ip) {
                unsigned long long a2 = ap[ip];
#pragma unroll
                for (int jx = 0; jx < 4; ++jx) FMA2(accp[ip][jx], a2, b2[jx]);
            }
        }
    }
#pragma unroll
    for (int ip = 0; ip < 4; ++ip) {
        int d = d0 + ty * 8 + 2 * ip;
        float4 v0 = make_float4(tanhf(lo2(accp[ip][0])), tanhf(lo2(accp[ip][1])),
                                tanhf(lo2(accp[ip][2])), tanhf(lo2(accp[ip][3])));
        float4 v1 = make_float4(tanhf(hi2(accp[ip][0])), tanhf(hi2(accp[ip][1])),
                                tanhf(hi2(accp[ip][2])), tanhf(hi2(accp[ip][3])));
        *(float4*)&g_beta[((size_t)s * DD + d) * BB + n0 + tx * 4] = v0;
        *(float4*)&g_beta[((size_t)s * DD + d + 1) * BB + n0 + tx * 4] = v1;
    }
}

// ---------------- ctx[b][d] = sum_s embedded[b][s][d] * beta[s][d][b] * alpha[b][s] ----------------
__global__ __launch_bounds__(128) void ctx_kernel() {
    const int d = blockIdx.x;
    const int b = threadIdx.x;
    float acc = 0.f;
    const float* em = g_embedded + (size_t)b * (SS * DD) + d;
    const float* bt = g_beta + (size_t)d * BB + b;
    const float* al = g_alpha + b * SS;
    for (int s = 0; s < SS; ++s)
        acc += em[(size_t)s * DD] * bt[(size_t)s * DD * BB] * al[s];
    g_ctx[b * DD + d] = acc;
}

// ---------------- out = ctx @ Wout^T ----------------
__global__ __launch_bounds__(128) void out_kernel(const float* __restrict__ Wout,
                                                  float* __restrict__ out) {
    const int b = blockIdx.x;
    const int n = threadIdx.x;
    __shared__ float cs[256];
    cs[n] = g_ctx[b * DD + n];
    cs[n + 128] = g_ctx[b * DD + n + 128];
    __syncthreads();
    float acc = 0.f;
    const float4* wp = (const float4*)(Wout + (size_t)n * DD);
#pragma unroll 8
    for (int d4 = 0; d4 < 64; ++d4) {
        float4 w = wp[d4];
        acc += cs[4 * d4] * w.x + cs[4 * d4 + 1] * w.y +
               cs[4 * d4 + 2] * w.z + cs[4 * d4 + 3] * w.w;
    }
    out[b * NC + n] = acc;
}

// ---------------- launch ----------------
extern "C" void kernel_launch(void* const* d_in, const int* in_sizes, int n_in,
                              void* d_out, int out_size) {
    (void)in_sizes; (void)n_in; (void)out_size;
    const float* inputs  = (const float*)d_in[0];
    const float* tstamp  = (const float*)d_in[1];
    const float* emb     = (const float*)d_in[2];
    const float* Wall1_w = (const float*)d_in[3];
    const float* Wall1_b = (const float*)d_in[4];
    const float* Uall1_w = (const float*)d_in[5];
    const float* Uall1_b = (const float*)d_in[6];
    const float* Wd1_w   = (const float*)d_in[7];
    const float* Wd1_b   = (const float*)d_in[8];
    const float* Wall2_w = (const float*)d_in[9];
    const float* Wall2_b = (const float*)d_in[10];
    const float* Uall2_w = (const float*)d_in[11];
    const float* Uall2_b = (const float*)d_in[12];
    const float* Wd2_w   = (const float*)d_in[13];
    const float* Wd2_b   = (const float*)d_in[14];
    const float* wa_w    = (const float*)d_in[15];
    const float* Wb_w    = (const float*)d_in[16];
    const float* Wout_w  = (const float*)d_in[17];
    const float* h01     = (const float*)d_in[18];
    const float* c01     = (const float*)d_in[19];
    const float* h02     = (const float*)d_in[20];
    const float* c02     = (const float*)d_in[21];
    float* out = (float*)d_out;

    init_kernel<<<128, 256>>>(h01, c01, h02, c02, tstamp);
    embed_gemm<<<dim3(4, 200), 256>>>(inputs, emb);
    ux_gemm<<<dim3(2, 8, 2 * SS), 256>>>(Uall1_w, Uall1_b, Wall1_b,
                                         Uall2_w, Uall2_b, Wall2_b);

    // persistent recurrence: cooperative launch guarantees all 128 blocks co-resident
    {
        cudaLaunchConfig_t cfg = {};
        cfg.gridDim = dim3(NBLK, 1, 1);
        cfg.blockDim = dim3(512, 1, 1);
        cfg.dynamicSmemBytes = 0;
        cfg.stream = 0;
        cudaLaunchAttribute attrs[1];
        attrs[0].id = cudaLaunchAttributeCooperative;
        attrs[0].val.cooperative = 1;
        cfg.attrs = attrs;
        cfg.numAttrs = 1;
        cudaLaunchKernelEx(&cfg, recur_kernel,
                           Wall1_w, Wd1_w, Wd1_b, Wall2_w, Wd2_w, Wd2_b);
    }

    alpha_kernel<<<128, 256>>>(wa_w);
    beta_gemm<<<dim3(2, 2, SS), 256>>>(Wb_w);
    ctx_kernel<<<256, 128>>>();
    out_kernel<<<128, 128>>>(Wout_w, out);
}